// round 3
// baseline (speedup 1.0000x reference)
#include <cuda_runtime.h>
#include <cuda_bf16.h>

// Scratch (no device allocs allowed).
__device__ double g_sum;
__device__ int    g_is64;   // 1 if target buffer is int64, 0 if int32

// Probe target dtype + zero the accumulator. Deterministic: depends only on input data.
__global__ void mrl_init_kernel(const int* __restrict__ t32) {
    g_sum = 0.0;
    // If the buffer is int64 with values in [0,128), every odd 32-bit word is 0.
    // If it's int32, odd words are random targets in [0,128): all-zero is impossible.
    int is64 = 1;
    #pragma unroll 4
    for (int i = 1; i < 256; i += 2) {
        if (t32[i] != 0) { is64 = 0; break; }
    }
    g_is64 = is64;
}

// x: [rows, 128] fp32. One warp per row, grid-stride.
__global__ void __launch_bounds__(256) mrl_main_kernel(
    const float* __restrict__ x,
    const void* __restrict__ target,
    int rows)
{
    const int lane   = threadIdx.x & 31;
    const int gwarp  = (blockIdx.x * blockDim.x + threadIdx.x) >> 5;
    const int nwarps = (gridDim.x * blockDim.x) >> 5;

    const int is64 = g_is64;
    const int*       t32 = (const int*)target;
    const long long* t64 = (const long long*)target;

    double local = 0.0;

    for (int r = gwarp; r < rows; r += nwarps) {
        const size_t base = (size_t)r * 128;
        // 32 lanes x float4 = 128 floats, fully coalesced.
        const float4 v = reinterpret_cast<const float4*>(x + base)[lane];
        const int tgt = is64 ? (int)t64[r] : t32[r];
        // Broadcast load of the positive score (all lanes same addr -> 1 txn).
        const float pos = __ldg(x + base + tgt);
        const float b   = 0.5f - pos;  // margin - pos

        float s = fmaxf(v.x + b, 0.0f)
                + fmaxf(v.y + b, 0.0f)
                + fmaxf(v.z + b, 0.0f)
                + fmaxf(v.w + b, 0.0f);

        // warp reduce
        #pragma unroll
        for (int o = 16; o > 0; o >>= 1)
            s += __shfl_xor_sync(0xFFFFFFFFu, s, o);

        // The target position itself contributed max(0, margin) = 0.5 exactly; remove it.
        if (lane == 0)
            local += (double)(s - 0.5f);
    }

    // Block reduction of per-warp doubles.
    __shared__ double ws[8];
    const int wid = threadIdx.x >> 5;
    if (lane == 0) ws[wid] = local;
    __syncthreads();
    if (threadIdx.x == 0) {
        double b = 0.0;
        #pragma unroll
        for (int i = 0; i < 8; i++) b += ws[i];
        atomicAdd(&g_sum, b);
    }
}

__global__ void mrl_fin_kernel(float* __restrict__ out, double inv_cnt) {
    out[0] = (float)(g_sum * inv_cnt);
}

extern "C" void kernel_launch(void* const* d_in, const int* in_sizes, int n_in,
                              void* d_out, int out_size)
{
    const float* x      = (const float*)d_in[0];   // [V, C, T] fp32
    const void*  target = d_in[1];                 // [V, C] int32 or int64 (auto-detected)
    float*       out    = (float*)d_out;

    const int T    = 128;
    const int rows = in_sizes[0] / T;              // V*C, derived from x so dtype doesn't matter
    const double cnt = (double)rows * (double)(T - 1);

    mrl_init_kernel<<<1, 1>>>((const int*)target);
    mrl_main_kernel<<<2368, 256>>>(x, target, rows);
    mrl_fin_kernel<<<1, 1>>>(out, 1.0 / cnt);
}

// round 4
// speedup vs baseline: 1.4825x; 1.4825x over previous
#include <cuda_runtime.h>
#include <cuda_bf16.h>

#define NBLOCKS 2048

// Scratch (no device allocs allowed).
__device__ double g_part[NBLOCKS];
__device__ int    g_is64;   // 1 if target buffer is int64, 0 if int32

// Warp-parallel dtype probe. If target is int64 with values in [0,128),
// every odd 32-bit word of the first 256 words is 0. If int32, the odd words
// are random targets in [0,128): P(all 128 zero) ~ (1/128)^128 ~ 0.
__global__ void mrl_init_kernel(const int* __restrict__ t32) {
    const int lane = threadIdx.x & 31;
    int nz = 0;
    #pragma unroll
    for (int j = 0; j < 4; j++)
        nz |= t32[1 + 2 * (lane * 4 + j)];
    unsigned any = __ballot_sync(0xFFFFFFFFu, nz != 0);
    if (lane == 0) g_is64 = (any == 0u) ? 1 : 0;
}

// x: [rows, 128] fp32. One warp per row, 4 rows per iteration, grid-stride.
// No per-row reduction: each lane accumulates privately; the target term's
// exact +0.5 contribution per row is removed analytically in the fin kernel.
__global__ void __launch_bounds__(256) mrl_main_kernel(
    const float* __restrict__ x,
    const void* __restrict__ target,
    int rows)
{
    const int lane   = threadIdx.x & 31;
    const int gwarp  = (blockIdx.x * blockDim.x + threadIdx.x) >> 5;
    const int nwarps = (gridDim.x * blockDim.x) >> 5;

    const int is64 = g_is64;
    const int*       t32 = (const int*)target;
    const long long* t64 = (const long long*)target;

    float a0 = 0.f, a1 = 0.f, a2 = 0.f, a3 = 0.f;

    int r = gwarp * 4;
    const int stride = nwarps * 4;

    // Main unrolled path: 4 full rows per iteration.
    for (; r + 3 < rows; r += stride) {
        int t0, t1, t2, t3;
        if (is64) {
            const longlong2 ta = *reinterpret_cast<const longlong2*>(t64 + r);
            const longlong2 tb = *reinterpret_cast<const longlong2*>(t64 + r + 2);
            t0 = (int)ta.x; t1 = (int)ta.y; t2 = (int)tb.x; t3 = (int)tb.y;
        } else {
            const int4 t = *reinterpret_cast<const int4*>(t32 + r);
            t0 = t.x; t1 = t.y; t2 = t.z; t3 = t.w;
        }

        const float* p = x + (size_t)r * 128;
        // Front-batched loads: 4 x LDG.128 per lane + 4 broadcast pos loads.
        const float4 v0 = reinterpret_cast<const float4*>(p        )[lane];
        const float4 v1 = reinterpret_cast<const float4*>(p + 128  )[lane];
        const float4 v2 = reinterpret_cast<const float4*>(p + 256  )[lane];
        const float4 v3 = reinterpret_cast<const float4*>(p + 384  )[lane];
        const float b0 = 0.5f - __ldg(p +       t0);
        const float b1 = 0.5f - __ldg(p + 128 + t1);
        const float b2 = 0.5f - __ldg(p + 256 + t2);
        const float b3 = 0.5f - __ldg(p + 384 + t3);

        a0 += fmaxf(v0.x + b0, 0.f) + fmaxf(v0.y + b0, 0.f)
            + fmaxf(v0.z + b0, 0.f) + fmaxf(v0.w + b0, 0.f);
        a1 += fmaxf(v1.x + b1, 0.f) + fmaxf(v1.y + b1, 0.f)
            + fmaxf(v1.z + b1, 0.f) + fmaxf(v1.w + b1, 0.f);
        a2 += fmaxf(v2.x + b2, 0.f) + fmaxf(v2.y + b2, 0.f)
            + fmaxf(v2.z + b2, 0.f) + fmaxf(v2.w + b2, 0.f);
        a3 += fmaxf(v3.x + b3, 0.f) + fmaxf(v3.y + b3, 0.f)
            + fmaxf(v3.z + b3, 0.f) + fmaxf(v3.w + b3, 0.f);
    }

    // Tail: remaining 0-3 rows.
    for (; r < rows; r++) {
        const int tgt = is64 ? (int)t64[r] : t32[r];
        const float* p = x + (size_t)r * 128;
        const float4 v = reinterpret_cast<const float4*>(p)[lane];
        const float b  = 0.5f - __ldg(p + tgt);
        a0 += fmaxf(v.x + b, 0.f) + fmaxf(v.y + b, 0.f)
            + fmaxf(v.z + b, 0.f) + fmaxf(v.w + b, 0.f);
    }

    // One reduction per kernel: lane partials -> warp -> block.
    double d = (double)a0 + (double)a1 + (double)a2 + (double)a3;
    #pragma unroll
    for (int o = 16; o > 0; o >>= 1)
        d += __shfl_xor_sync(0xFFFFFFFFu, d, o);

    __shared__ double ws[8];
    const int wid = threadIdx.x >> 5;
    if (lane == 0) ws[wid] = d;
    __syncthreads();
    if (threadIdx.x == 0) {
        double b = 0.0;
        #pragma unroll
        for (int i = 0; i < 8; i++) b += ws[i];
        g_part[blockIdx.x] = b;
    }
}

// Reduce NBLOCKS partials, subtract the exact 0.5-per-row target contribution.
__global__ void __launch_bounds__(256) mrl_fin_kernel(
    float* __restrict__ out, int rows, double inv_cnt)
{
    const int tid = threadIdx.x;
    double s = 0.0;
    #pragma unroll
    for (int i = tid; i < NBLOCKS; i += 256) s += g_part[i];

    #pragma unroll
    for (int o = 16; o > 0; o >>= 1)
        s += __shfl_xor_sync(0xFFFFFFFFu, s, o);

    __shared__ double ws[8];
    const int lane = tid & 31, wid = tid >> 5;
    if (lane == 0) ws[wid] = s;
    __syncthreads();
    if (tid == 0) {
        double b = 0.0;
        #pragma unroll
        for (int i = 0; i < 8; i++) b += ws[i];
        out[0] = (float)((b - 0.5 * (double)rows) * inv_cnt);
    }
}

extern "C" void kernel_launch(void* const* d_in, const int* in_sizes, int n_in,
                              void* d_out, int out_size)
{
    const float* x      = (const float*)d_in[0];   // [V, C, T] fp32
    const void*  target = d_in[1];                 // [V, C] int32 or int64 (auto-detected)
    float*       out    = (float*)d_out;

    const int T    = 128;
    const int rows = in_sizes[0] / T;              // V*C
    const double cnt = (double)rows * (double)(T - 1);

    mrl_init_kernel<<<1, 32>>>((const int*)target);
    mrl_main_kernel<<<NBLOCKS, 256>>>(x, target, rows);
    mrl_fin_kernel<<<1, 256>>>(out, rows, 1.0 / cnt);
}